// round 16
// baseline (speedup 1.0000x reference)
#include <cuda_runtime.h>
#include <cuda_bf16.h>
#include <cuda_fp16.h>

#define NU 200000
#define NR 200000
#define HDIM 64
#define EDGES 4000000
#define SCAN_B 1024
#define M2 (2 * NU)
#define NSCANB ((M2 + SCAN_B - 1) / SCAN_B)   // 391

typedef unsigned long long ull;
typedef unsigned int uint;

// ---------------- static device scratch (all features fp16) ----------------
__device__ __align__(16) __half g_uh16 [(size_t)NU * HDIM];   // user_emb fp16; reused as xu2 fp16
__device__ __align__(16) __half g_xr0h [(size_t)NR * HDIM];   // xr0 fp16; reused as final xr fp16
__device__ __align__(16) __half g_xr1h [(size_t)NR * HDIM];
__device__ __align__(16) __half g_xu1h [(size_t)NU * HDIM];
__device__ __align__(16) __half g_mean_rh [(size_t)NR * HDIM];
__device__ __align__(16) __half g_mean_uh [(size_t)NU * HDIM];
__device__ __align__(16) __half g_mean_r2h[(size_t)NR * HDIM];
__device__ __align__(16) __half g_mean_u2h[(size_t)NU * HDIM];
__device__ int   g_nbr_r[EDGES];
__device__ int   g_nbr_u[EDGES];
__device__ int   g_rank[EDGES];     // packed: lo16 = user rank, hi16 = recipe rank
__device__ int   g_off_u[NU + 1];
__device__ int   g_off_r[NR + 1];
__device__ int   g_deg[M2];
__device__ volatile ull g_scan_state[NSCANB];
// prepped W tiles, per transform: [hi: 64x128 bf16 (16KB)][lo: 64x128 bf16 (16KB)], layout n*128+k
__device__ __align__(16) unsigned char g_bw[4][32768];

// hi/lo bf16 split of a float2, packed as bf16x2 words
__device__ __forceinline__ void split2(float2 f, uint& hi, uint& lo) {
    __nv_bfloat162 h = __float22bfloat162_rn(f);
    float2 hf = __bfloat1622float2(h);
    __nv_bfloat162 l = __float22bfloat162_rn(make_float2(f.x - hf.x, f.y - hf.y));
    hi = *(uint*)&h;
    lo = *(uint*)&l;
}

// m16n8k16 row.col bf16 MMA, fp32 accum
__device__ __forceinline__ void mma16816(float* c, uint a0, uint a1, uint a2, uint a3,
                                         uint b0, uint b1) {
    asm volatile(
        "mma.sync.aligned.m16n8k16.row.col.f32.bf16.bf16.f32 "
        "{%0,%1,%2,%3}, {%4,%5,%6,%7}, {%8,%9}, {%0,%1,%2,%3};"
        : "+f"(c[0]), "+f"(c[1]), "+f"(c[2]), "+f"(c[3])
        : "r"(a0), "r"(a1), "r"(a2), "r"(a3), "r"(b0), "r"(b1));
}

// ---------------- merged prologue: count+ranks+fp16 convert | x_recipe init | W prep ----
__global__ void __launch_bounds__(256) k_pre(
    const int* __restrict__ ei, int* __restrict__ deg, int* __restrict__ rank,
    const float* __restrict__ ue, int e, int CB,
    const float* __restrict__ rx, const float* __restrict__ lw,
    const float* __restrict__ lb, const float* __restrict__ remb,
    __half* __restrict__ xout16, int IB,
    const float* __restrict__ Wl, const float* __restrict__ Wr) {
    int bid = blockIdx.x;
    int tid = threadIdx.x;
    __shared__ float slw[640];
    __shared__ float slb[64];

    if (bid < CB) {
        // ---- count + packed ranks + scan-state reset + user_emb fp16 mirror ----
        int i = bid * 256 + tid;
        if (bid == 0 && tid < NSCANB)
            *(ull*)&g_scan_state[tid] = 0ull;
        if (i < NU * 16) {
            float4 v = ((const float4*)ue)[i];
            __half2 h0 = __floats2half2_rn(v.x, v.y);
            __half2 h1 = __floats2half2_rn(v.z, v.w);
            ((uint2*)g_uh16)[i] = make_uint2(*(uint*)&h0, *(uint*)&h1);
        }
        if (i < e) {
            int ru = atomicAdd(&deg[ei[i]], 1);
            int rr = atomicAdd(&deg[NU + ei[e + i]], 1);
            rank[i] = ru | (rr << 16);
        }
        return;
    }
    if (bid < CB + IB) {
        // ---- x_recipe init (fp16 out) ----
        int ib = bid - CB;
        for (int i = tid; i < 640; i += 256) slw[i] = lw[i];
        if (tid < 64) slb[tid] = lb[tid];
        __syncthreads();
        int idx4 = ib * 256 + tid;
        if (idx4 >= NR * 16) return;
        int r = idx4 >> 4;
        int h0 = (idx4 & 15) * 4;
        float4 acc = make_float4(slb[h0], slb[h0 + 1], slb[h0 + 2], slb[h0 + 3]);
        const float* xr = rx + r * 10;
#pragma unroll
        for (int k = 0; k < 10; k++) {
            float xv = xr[k];
            const float* wr = slw + k * 64 + h0;
            acc.x = fmaf(xv, wr[0], acc.x);
            acc.y = fmaf(xv, wr[1], acc.y);
            acc.z = fmaf(xv, wr[2], acc.z);
            acc.w = fmaf(xv, wr[3], acc.w);
        }
        float4 ee = ((const float4*)remb)[idx4];
        acc.x += ee.x; acc.y += ee.y; acc.z += ee.z; acc.w += ee.w;
        __half2 ha = __floats2half2_rn(acc.x, acc.y);
        __half2 hb = __floats2half2_rn(acc.z, acc.w);
        ((uint2*)xout16)[idx4] = make_uint2(*(uint*)&ha, *(uint*)&hb);
        return;
    }
    // ---- weight prep: Wt[n][k] bf16 hi/lo ----
    {
        const int offs[4] = {0, 4096, 12288, 8192};  // T0:r0 T1:u0 T2:u1 T3:r1
        int b = bid - CB - IB;
        int off = offs[b];
        __nv_bfloat16* hi = (__nv_bfloat16*)g_bw[b];
        __nv_bfloat16* lo = hi + 8192;
        for (int i = tid; i < 8192; i += 256) {
            int n = i >> 7, k = i & 127;
            float w = (k < 64) ? Wl[off + k * 64 + n] : Wr[off + (k - 64) * 64 + n];
            __nv_bfloat16 h = __float2bfloat16(w);
            hi[i] = h;
            lo[i] = __float2bfloat16(w - __bfloat162float(h));
        }
    }
}

// ---------------- CSR: decoupled-lookback scan ----------------
__global__ void __launch_bounds__(SCAN_B) k_scan_lb(
    const int* __restrict__ deg, int* __restrict__ off_u, int* __restrict__ off_r,
    int n, int etot) {
    __shared__ int sh[SCAN_B];
    __shared__ int s_prefix;
    int b = blockIdx.x;
    int i = b * SCAN_B + threadIdx.x;
    int v = (i < n) ? deg[i] : 0;
    sh[threadIdx.x] = v;
    __syncthreads();
    for (int s = 1; s < SCAN_B; s <<= 1) {
        int t = (threadIdx.x >= s) ? sh[threadIdx.x - s] : 0;
        __syncthreads();
        sh[threadIdx.x] += t;
        __syncthreads();
    }
    int incl_local = sh[threadIdx.x];
    int total = sh[SCAN_B - 1];
    if (threadIdx.x == 0) {
        if (b == 0) {
            atomicExch((ull*)&g_scan_state[0], ((ull)2 << 32) | (unsigned)total);
            s_prefix = 0;
        } else {
            atomicExch((ull*)&g_scan_state[b], ((ull)1 << 32) | (unsigned)total);
            int prefix = 0;
            for (int p = b - 1; p >= 0;) {
                ull st;
                do { st = g_scan_state[p]; } while ((st >> 32) == 0);
                prefix += (int)(unsigned)st;
                if ((st >> 32) == 2) break;
                p--;
            }
            atomicExch((ull*)&g_scan_state[b], ((ull)2 << 32) | (unsigned)(prefix + total));
            s_prefix = prefix;
        }
    }
    __syncthreads();
    int excl = s_prefix + incl_local - v;
    if (i < n) {
        if (i < NU) off_u[i] = excl;
        else        off_r[i - NU] = excl - etot;
        if (i == NU) off_u[NU] = excl;
        if (i == n - 1) off_r[NR] = excl + v - etot;
    }
}

// ---------------- CSR fill: atomic-free via packed ranks ----------------
__global__ void k_fill(const int* __restrict__ ei,
                       const int* __restrict__ off_u, const int* __restrict__ off_r,
                       const int* __restrict__ rank,
                       int* __restrict__ nbr_u, int* __restrict__ nbr_r, int e) {
    int i = blockIdx.x * blockDim.x + threadIdx.x;
    if (i < e) {
        int s = ei[i], d = ei[e + i];
        int r = rank[i];
        nbr_u[off_u[s] + (r & 0xffff)] = d;
        nbr_r[off_r[d] + (r >> 16)] = s;
    }
}

// ---------------- fp16 mean aggregation core ----------------
// 16 neighbors/outer-iter, fp16 pairwise fold staged so only 2 uint4 live.
__device__ __forceinline__ void agg_node(
    int w, int lane, const int* __restrict__ off, const int* __restrict__ nbr,
    const __half* __restrict__ xsrc, __half* __restrict__ mean16) {
    int beg = off[w], end = off[w + 1];
    int q = lane >> 3;       // neighbor slot 0..3
    int c = lane & 7;        // 16B chunk within 128B row
    const uint4* X = (const uint4*)xsrc;   // row = 8 uint4
    float a[8];
#pragma unroll
    for (int i = 0; i < 8; i++) a[i] = 0.f;

    for (int j = beg; j < end; j += 32) {
        int cnt = end - j; if (cnt > 32) cnt = 32;
        int idx = (lane < cnt) ? nbr[j + lane] : 0;
        int t = 0;
        for (; t + 16 <= cnt; t += 16) {
            int r0 = __shfl_sync(0xffffffffu, idx, t + q);
            int r1 = __shfl_sync(0xffffffffu, idx, t + 4 + q);
            uint4 v0 = X[(size_t)r0 * 8 + c];
            uint4 v1 = X[(size_t)r1 * 8 + c];
            __half2 s0 = __hadd2(*(__half2*)&v0.x, *(__half2*)&v1.x);
            __half2 s1 = __hadd2(*(__half2*)&v0.y, *(__half2*)&v1.y);
            __half2 s2 = __hadd2(*(__half2*)&v0.z, *(__half2*)&v1.z);
            __half2 s3 = __hadd2(*(__half2*)&v0.w, *(__half2*)&v1.w);
            int r2 = __shfl_sync(0xffffffffu, idx, t + 8 + q);
            int r3 = __shfl_sync(0xffffffffu, idx, t + 12 + q);
            v0 = X[(size_t)r2 * 8 + c];
            v1 = X[(size_t)r3 * 8 + c];
            s0 = __hadd2(s0, __hadd2(*(__half2*)&v0.x, *(__half2*)&v1.x));
            s1 = __hadd2(s1, __hadd2(*(__half2*)&v0.y, *(__half2*)&v1.y));
            s2 = __hadd2(s2, __hadd2(*(__half2*)&v0.z, *(__half2*)&v1.z));
            s3 = __hadd2(s3, __hadd2(*(__half2*)&v0.w, *(__half2*)&v1.w));
            float2 f;
            f = __half22float2(s0); a[0] += f.x; a[1] += f.y;
            f = __half22float2(s1); a[2] += f.x; a[3] += f.y;
            f = __half22float2(s2); a[4] += f.x; a[5] += f.y;
            f = __half22float2(s3); a[6] += f.x; a[7] += f.y;
        }
        for (; t < cnt; t += 4) {
            int u = t + q;
            int r = __shfl_sync(0xffffffffu, idx, (u < cnt) ? u : t);
            if (u < cnt) {
                uint4 v = X[(size_t)r * 8 + c];
#pragma unroll
                for (int p = 0; p < 4; p++) {
                    uint uw = (&v.x)[p];
                    float2 f = __half22float2(*(__half2*)&uw);
                    a[2 * p]     += f.x;
                    a[2 * p + 1] += f.y;
                }
            }
        }
    }
#pragma unroll
    for (int i = 0; i < 8; i++) {
        a[i] += __shfl_down_sync(0xffffffffu, a[i], 16);
        a[i] += __shfl_down_sync(0xffffffffu, a[i], 8);
    }
    if (lane < 8) {
        float inv = 1.0f / fmaxf((float)(end - beg), 1.0f);
        __half2 h0 = __floats2half2_rn(a[0] * inv, a[1] * inv);
        __half2 h1 = __floats2half2_rn(a[2] * inv, a[3] * inv);
        __half2 h2 = __floats2half2_rn(a[4] * inv, a[5] * inv);
        __half2 h3 = __floats2half2_rn(a[6] * inv, a[7] * inv);
        ((uint4*)mean16)[(size_t)w * 8 + c] =
            make_uint4(*(uint*)&h0, *(uint*)&h1, *(uint*)&h2, *(uint*)&h3);
    }
}

// merged pair: blocks [0, gA) run job A, [gA, gA+gB) run job B
__global__ void __launch_bounds__(256) k_agg2(
    const int* __restrict__ offA, const int* __restrict__ nbrA,
    const __half* __restrict__ srcA, __half* __restrict__ dstA, int nA, int gA,
    const int* __restrict__ offB, const int* __restrict__ nbrB,
    const __half* __restrict__ srcB, __half* __restrict__ dstB, int nB) {
    int lane = threadIdx.x & 31;
    int wloc = threadIdx.x >> 5;
    if (blockIdx.x < (unsigned)gA) {
        int w = blockIdx.x * 8 + wloc;
        if (w < nA) agg_node(w, lane, offA, nbrA, srcA, dstA);
    } else {
        int w = (blockIdx.x - gA) * 8 + wloc;
        if (w < nB) agg_node(w, lane, offB, nbrB, srcB, dstB);
    }
}

// ---------------- HMMA transform core: fp16 in, fp16 out ----------------
#define KPADW 68                    // uint words per padded row (136 halves)
#define SA_W (128 * KPADW)          // A: 8704 words
#define SBH_W (SA_W)                // B hi plane offset
#define SBL_W (SA_W + 64 * KPADW)   // B lo plane offset
#define SM_WORDS (SA_W + 2 * 64 * KPADW)   // 17408 words = 69632 B

__device__ __forceinline__ void tmma_block(
    int tb, uint* smem,
    const __half* __restrict__ A0, const __half* __restrict__ A1,
    const unsigned char* __restrict__ bw,
    const float* __restrict__ bias, __half* __restrict__ out16, int n, int relu) {
    uint* sa = smem;
    uint* bh = smem + SBH_W;
    uint* bl = smem + SBL_W;
    const int tid = threadIdx.x;
    const int rbase = tb * 128;

    {
        const uint* bs = (const uint*)bw;
#pragma unroll
        for (int it = 0; it < 16; it++) {
            int u = tid + it * 256;
            int nn = u >> 6, kw = u & 63;
            int d = nn * KPADW + kw;
            bh[d] = bs[u];
            bl[d] = bs[4096 + u];
        }
    }

#pragma unroll
    for (int it = 0; it < 8; it++) {
        int idx4 = tid + it * 256;              // 0..2047
        int r = idx4 >> 4, qq = idx4 & 15;      // qq<8: A0, else A1
        int gr = rbase + r; if (gr >= n) gr = rbase;
        uint4 v = *(((const uint4*)((qq < 8 ? A0 : A1) + (size_t)gr * 64)) + (qq & 7));
        *(uint4*)(sa + r * KPADW + qq * 4) = v;
    }
    __syncthreads();

    const int wid = tid >> 5, lane = tid & 31;
    const int g = lane >> 2, tg = lane & 3;
    const int rowA = wid * 16 + g;
    const int rowA8 = rowA + 8;

    float acc[8][4];
#pragma unroll
    for (int j = 0; j < 8; j++)
#pragma unroll
        for (int q = 0; q < 4; q++) acc[j][q] = 0.f;

#pragma unroll
    for (int kk = 0; kk < 8; kk++) {
        int kw = kk * 8 + tg;
        uint x0 = sa[rowA * KPADW + kw];
        uint x1 = sa[rowA8 * KPADW + kw];
        uint x2 = sa[rowA * KPADW + kw + 4];
        uint x3 = sa[rowA8 * KPADW + kw + 4];
        uint ah0, ah1, ah2, ah3, al0, al1, al2, al3;
        split2(__half22float2(*(__half2*)&x0), ah0, al0);
        split2(__half22float2(*(__half2*)&x1), ah1, al1);
        split2(__half22float2(*(__half2*)&x2), ah2, al2);
        split2(__half22float2(*(__half2*)&x3), ah3, al3);
#pragma unroll
        for (int j = 0; j < 8; j++) {
            int nrow = j * 8 + g;
            uint bh0 = bh[nrow * KPADW + kw];
            uint bh1 = bh[nrow * KPADW + kw + 4];
            uint bl0 = bl[nrow * KPADW + kw];
            uint bl1 = bl[nrow * KPADW + kw + 4];
            mma16816(acc[j], ah0, ah1, ah2, ah3, bh0, bh1);
            mma16816(acc[j], al0, al1, al2, al3, bh0, bh1);
            mma16816(acc[j], ah0, ah1, ah2, ah3, bl0, bl1);
        }
    }

    int row1 = rbase + rowA;
    int row2 = row1 + 8;
#pragma unroll
    for (int j = 0; j < 8; j++) {
        int col = j * 8 + tg * 2;
        float2 bb = *(const float2*)(bias + col);
        float2 o1 = make_float2(acc[j][0] + bb.x, acc[j][1] + bb.y);
        float2 o2 = make_float2(acc[j][2] + bb.x, acc[j][3] + bb.y);
        if (relu) {
            o1.x = fmaxf(o1.x, 0.f); o1.y = fmaxf(o1.y, 0.f);
            o2.x = fmaxf(o2.x, 0.f); o2.y = fmaxf(o2.y, 0.f);
        }
        if (row1 < n) {
            __half2 p = __floats2half2_rn(o1.x, o1.y);
            *(__half2*)(out16 + (size_t)row1 * 64 + col) = p;
        }
        if (row2 < n) {
            __half2 p = __floats2half2_rn(o2.x, o2.y);
            *(__half2*)(out16 + (size_t)row2 * 64 + col) = p;
        }
    }
}

// merged pair of transforms (independent jobs, identical footprint)
__global__ void __launch_bounds__(256) k_tmma2(
    const __half* A0a, const __half* A1a, const unsigned char* bwa,
    const float* biasa, __half* outa, int na, int relua, int gA,
    const __half* A0b, const __half* A1b, const unsigned char* bwb,
    const float* biasb, __half* outb, int nb, int relub) {
    extern __shared__ uint smem[];
    if (blockIdx.x < (unsigned)gA)
        tmma_block(blockIdx.x, smem, A0a, A1a, bwa, biasa, outa, na, relua);
    else
        tmma_block(blockIdx.x - gA, smem, A0b, A1b, bwb, biasb, outb, nb, relub);
}

// ---------------- classifier: quarter-warp per label edge, fp16 inputs ----------------
__global__ void __launch_bounds__(256) k_classify_h(
    const int* __restrict__ eli, const __half* __restrict__ xu,
    const __half* __restrict__ xr, float* __restrict__ out, int nl) {
    int qw = (blockIdx.x * blockDim.x + threadIdx.x) >> 3;
    int ql = threadIdx.x & 7;
    if (qw >= nl) return;
    int a = eli[qw], b = eli[nl + qw];
    uint4 va = ((const uint4*)xu)[(size_t)a * 8 + ql];
    uint4 vb = ((const uint4*)xr)[(size_t)b * 8 + ql];
    float s = 0.f;
#pragma unroll
    for (int p = 0; p < 4; p++) {
        float2 fa = __half22float2(*(__half2*)&(&va.x)[p]);
        float2 fb = __half22float2(*(__half2*)&(&vb.x)[p]);
        s = fmaf(fa.x, fb.x, s);
        s = fmaf(fa.y, fb.y, s);
    }
    s += __shfl_down_sync(0xffffffffu, s, 4, 8);
    s += __shfl_down_sync(0xffffffffu, s, 2, 8);
    s += __shfl_down_sync(0xffffffffu, s, 1, 8);
    if (ql == 0) out[qw] = s;
}

// ---------------- launch ----------------
extern "C" void kernel_launch(void* const* d_in, const int* in_sizes, int n_in,
                              void* d_out, int out_size) {
    const float* recipe_x   = (const float*)d_in[2];
    const int*   edge_index = (const int*)d_in[3];
    const int*   eli        = (const int*)d_in[4];
    const float* user_emb   = (const float*)d_in[5];
    const float* recipe_emb = (const float*)d_in[6];
    const float* lin_w      = (const float*)d_in[7];
    const float* lin_b      = (const float*)d_in[8];
    const float* Wl         = (const float*)d_in[9];
    const float* bl         = (const float*)d_in[10];
    const float* Wr         = (const float*)d_in[11];
    float* out = (float*)d_out;
    int E_ = in_sizes[3] / 2;
    int L_ = in_sizes[4] / 2;

    __half *uh16, *xr0h, *xr1h, *xu1h, *mean_rh, *mean_uh, *mean_r2h, *mean_u2h;
    int *nbr_r, *nbr_u, *rank, *off_u, *off_r, *deg;
    unsigned char* bw;
    cudaGetSymbolAddress((void**)&uh16,     g_uh16);
    cudaGetSymbolAddress((void**)&xr0h,     g_xr0h);
    cudaGetSymbolAddress((void**)&xr1h,     g_xr1h);
    cudaGetSymbolAddress((void**)&xu1h,     g_xu1h);
    cudaGetSymbolAddress((void**)&mean_rh,  g_mean_rh);
    cudaGetSymbolAddress((void**)&mean_uh,  g_mean_uh);
    cudaGetSymbolAddress((void**)&mean_r2h, g_mean_r2h);
    cudaGetSymbolAddress((void**)&mean_u2h, g_mean_u2h);
    cudaGetSymbolAddress((void**)&nbr_r,    g_nbr_r);
    cudaGetSymbolAddress((void**)&nbr_u,    g_nbr_u);
    cudaGetSymbolAddress((void**)&rank,     g_rank);
    cudaGetSymbolAddress((void**)&off_u,    g_off_u);
    cudaGetSymbolAddress((void**)&off_r,    g_off_r);
    cudaGetSymbolAddress((void**)&deg,      g_deg);
    cudaGetSymbolAddress((void**)&bw,       g_bw);

    const int TM_SMEM = SM_WORDS * 4;   // 69632 B
    cudaFuncSetAttribute(k_tmma2, cudaFuncAttributeMaxDynamicSharedMemorySize, TM_SMEM);

    const int TMB  = (NU + 127) / 128;           // 1563
    const int AGGB = (NR * 32 + 255) / 256;      // 25000
    const int CB   = (E_ + 255) / 256;           // 15625 (covers NU*16=3.2M too)
    const int IB   = (NR * 16 + 255) / 256;      // 12500

    cudaMemsetAsync(deg, 0, M2 * sizeof(int), 0);

    // merged prologue: count(+ranks,+fp16 mirror) | init_recipe | prep_w
    k_pre<<<CB + IB + 4, 256>>>(edge_index, deg, rank, user_emb, E_, CB,
                                recipe_x, lin_w, lin_b, recipe_emb, xr0h, IB,
                                Wl, Wr);

    k_scan_lb<<<NSCANB, SCAN_B>>>(deg, off_u, off_r, M2, E_);
    k_fill   <<<(E_ + 255) / 256, 256>>>(edge_index, off_u, off_r, rank,
                                         nbr_u, nbr_r, E_);

    // layer-0 aggregations (merged: agg_r0 || agg_u0)
    k_agg2<<<2 * AGGB, 256>>>(off_r, nbr_r, uh16, mean_rh, NR, AGGB,
                              off_u, nbr_u, xr0h, mean_uh, NU);

    // layer-0 transforms (merged, relu)
    k_tmma2<<<2 * TMB, 256, TM_SMEM>>>(
        mean_rh, xr0h, bw + 0 * 32768, bl,      xr1h, NR, 1, TMB,
        mean_uh, uh16, bw + 1 * 32768, bl + 64, xu1h, NU, 1);

    // layer-1 aggregations (merged)
    k_agg2<<<2 * AGGB, 256>>>(off_u, nbr_u, xr1h, mean_u2h, NU, AGGB,
                              off_r, nbr_r, xu1h, mean_r2h, NR);

    // layer-1 transforms (merged; outputs reuse uh16/xr0h — last read above)
    k_tmma2<<<2 * TMB, 256, TM_SMEM>>>(
        mean_u2h, xu1h, bw + 2 * 32768, bl + 192, uh16, NU, 0, TMB,
        mean_r2h, xr1h, bw + 3 * 32768, bl + 128, xr0h, NR, 0);

    // classifier
    k_classify_h<<<(L_ * 8 + 255) / 256, 256>>>(eli, uh16, xr0h, out, L_);
}

// round 17
// speedup vs baseline: 1.1077x; 1.1077x over previous
#include <cuda_runtime.h>
#include <cuda_bf16.h>
#include <cuda_fp16.h>

#define NU 200000
#define NR 200000
#define HDIM 64
#define EDGES 4000000
#define SCAN_B 1024
#define M2 (2 * NU)
#define NSCANB ((M2 + SCAN_B - 1) / SCAN_B)   // 391

typedef unsigned long long ull;
typedef unsigned int uint;

// ---------------- static device scratch (all features fp16) ----------------
__device__ __align__(16) __half g_uh16 [(size_t)NU * HDIM];   // user_emb fp16; reused as xu2 fp16
__device__ __align__(16) __half g_xr0h [(size_t)NR * HDIM];   // xr0 fp16; reused as final xr fp16
__device__ __align__(16) __half g_xr1h [(size_t)NR * HDIM];
__device__ __align__(16) __half g_xu1h [(size_t)NU * HDIM];
__device__ __align__(16) __half g_mean_rh [(size_t)NR * HDIM];
__device__ __align__(16) __half g_mean_uh [(size_t)NU * HDIM];
__device__ __align__(16) __half g_mean_r2h[(size_t)NR * HDIM];
__device__ __align__(16) __half g_mean_u2h[(size_t)NU * HDIM];
__device__ int   g_nbr_r[EDGES];
__device__ int   g_nbr_u[EDGES];
__device__ int   g_rank[EDGES];     // packed: lo16 = user rank, hi16 = recipe rank
__device__ int   g_off_u[NU + 1];
__device__ int   g_off_r[NR + 1];
__device__ int   g_deg[M2];
__device__ volatile ull g_scan_state[NSCANB];
// prepped W tiles, per transform: [hi: 64x128 bf16 (16KB)][lo: 64x128 bf16 (16KB)], layout n*128+k
__device__ __align__(16) unsigned char g_bw[4][32768];

// hi/lo bf16 split of a float2, packed as bf16x2 words
__device__ __forceinline__ void split2(float2 f, uint& hi, uint& lo) {
    __nv_bfloat162 h = __float22bfloat162_rn(f);
    float2 hf = __bfloat1622float2(h);
    __nv_bfloat162 l = __float22bfloat162_rn(make_float2(f.x - hf.x, f.y - hf.y));
    hi = *(uint*)&h;
    lo = *(uint*)&l;
}

// m16n8k16 row.col bf16 MMA, fp32 accum
__device__ __forceinline__ void mma16816(float* c, uint a0, uint a1, uint a2, uint a3,
                                         uint b0, uint b1) {
    asm volatile(
        "mma.sync.aligned.m16n8k16.row.col.f32.bf16.bf16.f32 "
        "{%0,%1,%2,%3}, {%4,%5,%6,%7}, {%8,%9}, {%0,%1,%2,%3};"
        : "+f"(c[0]), "+f"(c[1]), "+f"(c[2]), "+f"(c[3])
        : "r"(a0), "r"(a1), "r"(a2), "r"(a3), "r"(b0), "r"(b1));
}

// ---------------- merged prologue: count+ranks+fp16 convert | x_recipe init | W prep ----
__global__ void __launch_bounds__(256) k_pre(
    const int* __restrict__ ei, int* __restrict__ deg, int* __restrict__ rank,
    const float* __restrict__ ue, int e, int CB,
    const float* __restrict__ rx, const float* __restrict__ lw,
    const float* __restrict__ lb, const float* __restrict__ remb,
    __half* __restrict__ xout16, int IB,
    const float* __restrict__ Wl, const float* __restrict__ Wr) {
    int bid = blockIdx.x;
    int tid = threadIdx.x;
    __shared__ float slw[640];
    __shared__ float slb[64];

    if (bid < CB) {
        int i = bid * 256 + tid;
        if (bid == 0 && tid < NSCANB)
            *(ull*)&g_scan_state[tid] = 0ull;
        if (i < NU * 16) {
            float4 v = ((const float4*)ue)[i];
            __half2 h0 = __floats2half2_rn(v.x, v.y);
            __half2 h1 = __floats2half2_rn(v.z, v.w);
            ((uint2*)g_uh16)[i] = make_uint2(*(uint*)&h0, *(uint*)&h1);
        }
        if (i < e) {
            int ru = atomicAdd(&deg[ei[i]], 1);
            int rr = atomicAdd(&deg[NU + ei[e + i]], 1);
            rank[i] = ru | (rr << 16);
        }
        return;
    }
    if (bid < CB + IB) {
        int ib = bid - CB;
        for (int i = tid; i < 640; i += 256) slw[i] = lw[i];
        if (tid < 64) slb[tid] = lb[tid];
        __syncthreads();
        int idx4 = ib * 256 + tid;
        if (idx4 >= NR * 16) return;
        int r = idx4 >> 4;
        int h0 = (idx4 & 15) * 4;
        float4 acc = make_float4(slb[h0], slb[h0 + 1], slb[h0 + 2], slb[h0 + 3]);
        const float* xr = rx + r * 10;
#pragma unroll
        for (int k = 0; k < 10; k++) {
            float xv = xr[k];
            const float* wr = slw + k * 64 + h0;
            acc.x = fmaf(xv, wr[0], acc.x);
            acc.y = fmaf(xv, wr[1], acc.y);
            acc.z = fmaf(xv, wr[2], acc.z);
            acc.w = fmaf(xv, wr[3], acc.w);
        }
        float4 ee = ((const float4*)remb)[idx4];
        acc.x += ee.x; acc.y += ee.y; acc.z += ee.z; acc.w += ee.w;
        __half2 ha = __floats2half2_rn(acc.x, acc.y);
        __half2 hb = __floats2half2_rn(acc.z, acc.w);
        ((uint2*)xout16)[idx4] = make_uint2(*(uint*)&ha, *(uint*)&hb);
        return;
    }
    {
        const int offs[4] = {0, 4096, 12288, 8192};  // T0:r0 T1:u0 T2:u1 T3:r1
        int b = bid - CB - IB;
        int off = offs[b];
        __nv_bfloat16* hi = (__nv_bfloat16*)g_bw[b];
        __nv_bfloat16* lo = hi + 8192;
        for (int i = tid; i < 8192; i += 256) {
            int n = i >> 7, k = i & 127;
            float w = (k < 64) ? Wl[off + k * 64 + n] : Wr[off + (k - 64) * 64 + n];
            __nv_bfloat16 h = __float2bfloat16(w);
            hi[i] = h;
            lo[i] = __float2bfloat16(w - __bfloat162float(h));
        }
    }
}

// ---------------- CSR: decoupled-lookback scan ----------------
__global__ void __launch_bounds__(SCAN_B) k_scan_lb(
    const int* __restrict__ deg, int* __restrict__ off_u, int* __restrict__ off_r,
    int n, int etot) {
    __shared__ int sh[SCAN_B];
    __shared__ int s_prefix;
    int b = blockIdx.x;
    int i = b * SCAN_B + threadIdx.x;
    int v = (i < n) ? deg[i] : 0;
    sh[threadIdx.x] = v;
    __syncthreads();
    for (int s = 1; s < SCAN_B; s <<= 1) {
        int t = (threadIdx.x >= s) ? sh[threadIdx.x - s] : 0;
        __syncthreads();
        sh[threadIdx.x] += t;
        __syncthreads();
    }
    int incl_local = sh[threadIdx.x];
    int total = sh[SCAN_B - 1];
    if (threadIdx.x == 0) {
        if (b == 0) {
            atomicExch((ull*)&g_scan_state[0], ((ull)2 << 32) | (unsigned)total);
            s_prefix = 0;
        } else {
            atomicExch((ull*)&g_scan_state[b], ((ull)1 << 32) | (unsigned)total);
            int prefix = 0;
            for (int p = b - 1; p >= 0;) {
                ull st;
                do { st = g_scan_state[p]; } while ((st >> 32) == 0);
                prefix += (int)(unsigned)st;
                if ((st >> 32) == 2) break;
                p--;
            }
            atomicExch((ull*)&g_scan_state[b], ((ull)2 << 32) | (unsigned)(prefix + total));
            s_prefix = prefix;
        }
    }
    __syncthreads();
    int excl = s_prefix + incl_local - v;
    if (i < n) {
        if (i < NU) off_u[i] = excl;
        else        off_r[i - NU] = excl - etot;
        if (i == NU) off_u[NU] = excl;
        if (i == n - 1) off_r[NR] = excl + v - etot;
    }
}

// ---------------- CSR fill: atomic-free via packed ranks ----------------
__global__ void k_fill(const int* __restrict__ ei,
                       const int* __restrict__ off_u, const int* __restrict__ off_r,
                       const int* __restrict__ rank,
                       int* __restrict__ nbr_u, int* __restrict__ nbr_r, int e) {
    int i = blockIdx.x * blockDim.x + threadIdx.x;
    if (i < e) {
        int s = ei[i], d = ei[e + i];
        int r = rank[i];
        nbr_u[off_u[s] + (r & 0xffff)] = d;
        nbr_r[off_r[d] + (r >> 16)] = s;
    }
}

// ---------------- fp16 mean aggregation core (R15 8-neighbor form, 32 regs) ----------------
__device__ __forceinline__ void agg_node(
    int w, int lane, const int* __restrict__ off, const int* __restrict__ nbr,
    const __half* __restrict__ xsrc, __half* __restrict__ mean16) {
    int beg = off[w], end = off[w + 1];
    int q = lane >> 3;       // neighbor slot 0..3
    int c = lane & 7;        // 16B chunk within 128B row
    const uint4* X = (const uint4*)xsrc;   // row = 8 uint4
    float a[8];
#pragma unroll
    for (int i = 0; i < 8; i++) a[i] = 0.f;

    for (int j = beg; j < end; j += 32) {
        int cnt = end - j; if (cnt > 32) cnt = 32;
        int idx = (lane < cnt) ? nbr[j + lane] : 0;
        int t = 0;
        for (; t + 8 <= cnt; t += 8) {
            int r0 = __shfl_sync(0xffffffffu, idx, t + q);
            int r1 = __shfl_sync(0xffffffffu, idx, t + 4 + q);
            uint4 v0 = X[(size_t)r0 * 8 + c];
            uint4 v1 = X[(size_t)r1 * 8 + c];
#pragma unroll
            for (int p = 0; p < 4; p++) {
                uint uw0 = (&v0.x)[p], uw1 = (&v1.x)[p];
                __half2 s = __hadd2(*(__half2*)&uw0, *(__half2*)&uw1);
                float2 f = __half22float2(s);
                a[2 * p]     += f.x;
                a[2 * p + 1] += f.y;
            }
        }
        for (; t < cnt; t += 4) {
            int u = t + q;
            int r = __shfl_sync(0xffffffffu, idx, (u < cnt) ? u : t);
            if (u < cnt) {
                uint4 v = X[(size_t)r * 8 + c];
#pragma unroll
                for (int p = 0; p < 4; p++) {
                    uint uw = (&v.x)[p];
                    float2 f = __half22float2(*(__half2*)&uw);
                    a[2 * p]     += f.x;
                    a[2 * p + 1] += f.y;
                }
            }
        }
    }
#pragma unroll
    for (int i = 0; i < 8; i++) {
        a[i] += __shfl_down_sync(0xffffffffu, a[i], 16);
        a[i] += __shfl_down_sync(0xffffffffu, a[i], 8);
    }
    if (lane < 8) {
        float inv = 1.0f / fmaxf((float)(end - beg), 1.0f);
        __half2 h0 = __floats2half2_rn(a[0] * inv, a[1] * inv);
        __half2 h1 = __floats2half2_rn(a[2] * inv, a[3] * inv);
        __half2 h2 = __floats2half2_rn(a[4] * inv, a[5] * inv);
        __half2 h3 = __floats2half2_rn(a[6] * inv, a[7] * inv);
        ((uint4*)mean16)[(size_t)w * 8 + c] =
            make_uint4(*(uint*)&h0, *(uint*)&h1, *(uint*)&h2, *(uint*)&h3);
    }
}

// merged pair: blocks [0, gA) run job A, [gA, gA+gB) run job B
__global__ void __launch_bounds__(256) k_agg2(
    const int* __restrict__ offA, const int* __restrict__ nbrA,
    const __half* __restrict__ srcA, __half* __restrict__ dstA, int nA, int gA,
    const int* __restrict__ offB, const int* __restrict__ nbrB,
    const __half* __restrict__ srcB, __half* __restrict__ dstB, int nB) {
    int lane = threadIdx.x & 31;
    int wloc = threadIdx.x >> 5;
    if (blockIdx.x < (unsigned)gA) {
        int w = blockIdx.x * 8 + wloc;
        if (w < nA) agg_node(w, lane, offA, nbrA, srcA, dstA);
    } else {
        int w = (blockIdx.x - gA) * 8 + wloc;
        if (w < nB) agg_node(w, lane, offB, nbrB, srcB, dstB);
    }
}

// ---------------- HMMA transform core: fp16 in, fp16 out ----------------
#define KPADW 68                    // uint words per padded row (136 halves)
#define SA_W (128 * KPADW)          // A: 8704 words
#define SBH_W (SA_W)                // B hi plane offset
#define SBL_W (SA_W + 64 * KPADW)   // B lo plane offset
#define SM_WORDS (SA_W + 2 * 64 * KPADW)   // 17408 words = 69632 B

__device__ __forceinline__ void tmma_block(
    int tb, uint* smem,
    const __half* __restrict__ A0, const __half* __restrict__ A1,
    const unsigned char* __restrict__ bw,
    const float* __restrict__ bias, __half* __restrict__ out16, int n, int relu) {
    uint* sa = smem;
    uint* bh = smem + SBH_W;
    uint* bl = smem + SBL_W;
    const int tid = threadIdx.x;
    const int rbase = tb * 128;

    {
        const uint* bs = (const uint*)bw;
#pragma unroll
        for (int it = 0; it < 16; it++) {
            int u = tid + it * 256;
            int nn = u >> 6, kw = u & 63;
            int d = nn * KPADW + kw;
            bh[d] = bs[u];
            bl[d] = bs[4096 + u];
        }
    }

#pragma unroll
    for (int it = 0; it < 8; it++) {
        int idx4 = tid + it * 256;              // 0..2047
        int r = idx4 >> 4, qq = idx4 & 15;      // qq<8: A0, else A1
        int gr = rbase + r; if (gr >= n) gr = rbase;
        uint4 v = *(((const uint4*)((qq < 8 ? A0 : A1) + (size_t)gr * 64)) + (qq & 7));
        *(uint4*)(sa + r * KPADW + qq * 4) = v;
    }
    __syncthreads();

    const int wid = tid >> 5, lane = tid & 31;
    const int g = lane >> 2, tg = lane & 3;
    const int rowA = wid * 16 + g;
    const int rowA8 = rowA + 8;

    float acc[8][4];
#pragma unroll
    for (int j = 0; j < 8; j++)
#pragma unroll
        for (int q = 0; q < 4; q++) acc[j][q] = 0.f;

#pragma unroll
    for (int kk = 0; kk < 8; kk++) {
        int kw = kk * 8 + tg;
        uint x0 = sa[rowA * KPADW + kw];
        uint x1 = sa[rowA8 * KPADW + kw];
        uint x2 = sa[rowA * KPADW + kw + 4];
        uint x3 = sa[rowA8 * KPADW + kw + 4];
        uint ah0, ah1, ah2, ah3, al0, al1, al2, al3;
        split2(__half22float2(*(__half2*)&x0), ah0, al0);
        split2(__half22float2(*(__half2*)&x1), ah1, al1);
        split2(__half22float2(*(__half2*)&x2), ah2, al2);
        split2(__half22float2(*(__half2*)&x3), ah3, al3);
#pragma unroll
        for (int j = 0; j < 8; j++) {
            int nrow = j * 8 + g;
            uint bh0 = bh[nrow * KPADW + kw];
            uint bh1 = bh[nrow * KPADW + kw + 4];
            uint bl0 = bl[nrow * KPADW + kw];
            uint bl1 = bl[nrow * KPADW + kw + 4];
            mma16816(acc[j], ah0, ah1, ah2, ah3, bh0, bh1);
            mma16816(acc[j], al0, al1, al2, al3, bh0, bh1);
            mma16816(acc[j], ah0, ah1, ah2, ah3, bl0, bl1);
        }
    }

    int row1 = rbase + rowA;
    int row2 = row1 + 8;
#pragma unroll
    for (int j = 0; j < 8; j++) {
        int col = j * 8 + tg * 2;
        float2 bb = *(const float2*)(bias + col);
        float2 o1 = make_float2(acc[j][0] + bb.x, acc[j][1] + bb.y);
        float2 o2 = make_float2(acc[j][2] + bb.x, acc[j][3] + bb.y);
        if (relu) {
            o1.x = fmaxf(o1.x, 0.f); o1.y = fmaxf(o1.y, 0.f);
            o2.x = fmaxf(o2.x, 0.f); o2.y = fmaxf(o2.y, 0.f);
        }
        if (row1 < n) {
            __half2 p = __floats2half2_rn(o1.x, o1.y);
            *(__half2*)(out16 + (size_t)row1 * 64 + col) = p;
        }
        if (row2 < n) {
            __half2 p = __floats2half2_rn(o2.x, o2.y);
            *(__half2*)(out16 + (size_t)row2 * 64 + col) = p;
        }
    }
}

// merged pair of transforms (independent jobs, identical footprint)
__global__ void __launch_bounds__(256) k_tmma2(
    const __half* A0a, const __half* A1a, const unsigned char* bwa,
    const float* biasa, __half* outa, int na, int relua, int gA,
    const __half* A0b, const __half* A1b, const unsigned char* bwb,
    const float* biasb, __half* outb, int nb, int relub) {
    extern __shared__ uint smem[];
    if (blockIdx.x < (unsigned)gA)
        tmma_block(blockIdx.x, smem, A0a, A1a, bwa, biasa, outa, na, relua);
    else
        tmma_block(blockIdx.x - gA, smem, A0b, A1b, bwb, biasb, outb, nb, relub);
}

// ---------------- classifier: quarter-warp per label edge, fp16 inputs ----------------
__global__ void __launch_bounds__(256) k_classify_h(
    const int* __restrict__ eli, const __half* __restrict__ xu,
    const __half* __restrict__ xr, float* __restrict__ out, int nl) {
    int qw = (blockIdx.x * blockDim.x + threadIdx.x) >> 3;
    int ql = threadIdx.x & 7;
    if (qw >= nl) return;
    int a = eli[qw], b = eli[nl + qw];
    uint4 va = ((const uint4*)xu)[(size_t)a * 8 + ql];
    uint4 vb = ((const uint4*)xr)[(size_t)b * 8 + ql];
    float s = 0.f;
#pragma unroll
    for (int p = 0; p < 4; p++) {
        float2 fa = __half22float2(*(__half2*)&(&va.x)[p]);
        float2 fb = __half22float2(*(__half2*)&(&vb.x)[p]);
        s = fmaf(fa.x, fb.x, s);
        s = fmaf(fa.y, fb.y, s);
    }
    s += __shfl_down_sync(0xffffffffu, s, 4, 8);
    s += __shfl_down_sync(0xffffffffu, s, 2, 8);
    s += __shfl_down_sync(0xffffffffu, s, 1, 8);
    if (ql == 0) out[qw] = s;
}

// ---------------- launch ----------------
extern "C" void kernel_launch(void* const* d_in, const int* in_sizes, int n_in,
                              void* d_out, int out_size) {
    const float* recipe_x   = (const float*)d_in[2];
    const int*   edge_index = (const int*)d_in[3];
    const int*   eli        = (const int*)d_in[4];
    const float* user_emb   = (const float*)d_in[5];
    const float* recipe_emb = (const float*)d_in[6];
    const float* lin_w      = (const float*)d_in[7];
    const float* lin_b      = (const float*)d_in[8];
    const float* Wl         = (const float*)d_in[9];
    const float* bl         = (const float*)d_in[10];
    const float* Wr         = (const float*)d_in[11];
    float* out = (float*)d_out;
    int E_ = in_sizes[3] / 2;
    int L_ = in_sizes[4] / 2;

    __half *uh16, *xr0h, *xr1h, *xu1h, *mean_rh, *mean_uh, *mean_r2h, *mean_u2h;
    int *nbr_r, *nbr_u, *rank, *off_u, *off_r, *deg;
    unsigned char* bw;
    cudaGetSymbolAddress((void**)&uh16,     g_uh16);
    cudaGetSymbolAddress((void**)&xr0h,     g_xr0h);
    cudaGetSymbolAddress((void**)&xr1h,     g_xr1h);
    cudaGetSymbolAddress((void**)&xu1h,     g_xu1h);
    cudaGetSymbolAddress((void**)&mean_rh,  g_mean_rh);
    cudaGetSymbolAddress((void**)&mean_uh,  g_mean_uh);
    cudaGetSymbolAddress((void**)&mean_r2h, g_mean_r2h);
    cudaGetSymbolAddress((void**)&mean_u2h, g_mean_u2h);
    cudaGetSymbolAddress((void**)&nbr_r,    g_nbr_r);
    cudaGetSymbolAddress((void**)&nbr_u,    g_nbr_u);
    cudaGetSymbolAddress((void**)&rank,     g_rank);
    cudaGetSymbolAddress((void**)&off_u,    g_off_u);
    cudaGetSymbolAddress((void**)&off_r,    g_off_r);
    cudaGetSymbolAddress((void**)&deg,      g_deg);
    cudaGetSymbolAddress((void**)&bw,       g_bw);

    const int TM_SMEM = SM_WORDS * 4;   // 69632 B
    cudaFuncSetAttribute(k_tmma2, cudaFuncAttributeMaxDynamicSharedMemorySize, TM_SMEM);

    const int TMB  = (NU + 127) / 128;           // 1563
    const int AGGB = (NR * 32 + 255) / 256;      // 25000
    const int CB   = (E_ + 255) / 256;           // 15625 (covers NU*16=3.2M too)
    const int IB   = (NR * 16 + 255) / 256;      // 12500

    cudaMemsetAsync(deg, 0, M2 * sizeof(int), 0);

    // merged prologue: count(+ranks,+fp16 mirror) | init_recipe | prep_w
    k_pre<<<CB + IB + 4, 256>>>(edge_index, deg, rank, user_emb, E_, CB,
                                recipe_x, lin_w, lin_b, recipe_emb, xr0h, IB,
                                Wl, Wr);

    k_scan_lb<<<NSCANB, SCAN_B>>>(deg, off_u, off_r, M2, E_);
    k_fill   <<<(E_ + 255) / 256, 256>>>(edge_index, off_u, off_r, rank,
                                         nbr_u, nbr_r, E_);

    // layer-0 aggregations (merged: agg_r0 || agg_u0)
    k_agg2<<<2 * AGGB, 256>>>(off_r, nbr_r, uh16, mean_rh, NR, AGGB,
                              off_u, nbr_u, xr0h, mean_uh, NU);

    // layer-0 transforms (merged, relu)
    k_tmma2<<<2 * TMB, 256, TM_SMEM>>>(
        mean_rh, xr0h, bw + 0 * 32768, bl,      xr1h, NR, 1, TMB,
        mean_uh, uh16, bw + 1 * 32768, bl + 64, xu1h, NU, 1);

    // layer-1 aggregations (merged)
    k_agg2<<<2 * AGGB, 256>>>(off_u, nbr_u, xr1h, mean_u2h, NU, AGGB,
                              off_r, nbr_r, xu1h, mean_r2h, NR);

    // layer-1 transforms (merged; outputs reuse uh16/xr0h — last read above)
    k_tmma2<<<2 * TMB, 256, TM_SMEM>>>(
        mean_u2h, xu1h, bw + 2 * 32768, bl + 192, uh16, NU, 0, TMB,
        mean_r2h, xr1h, bw + 3 * 32768, bl + 128, xr0h, NR, 0);

    // classifier
    k_classify_h<<<(L_ * 8 + 255) / 256, 256>>>(eli, uh16, xr0h, out, L_);
}